// round 2
// baseline (speedup 1.0000x reference)
#include <cuda_runtime.h>
#include <cuda_bf16.h>

// Scratch (no cudaMalloc allowed): transform matrix, its diagonal, and a
// "matrix is diagonal" flag, computed fresh every launch by prep_kernel.
__device__ float g_ht[256];    // h_t[j][i] = hadamard[j][i] * signs[j]
__device__ float g_diag[16];
__device__ int   g_is_diag;

// One block, 256 threads: thread t handles element (j = t/16, i = t%16).
__global__ void had_prep_kernel(const float* __restrict__ hadamard,
                                const float* __restrict__ signs) {
    __shared__ int s_offdiag;
    int t = threadIdx.x;
    int j = t >> 4;
    int i = t & 15;
    if (t == 0) s_offdiag = 0;
    __syncthreads();
    float v = hadamard[t] * signs[j];
    g_ht[t] = v;
    if (i == j) g_diag[j] = v;
    if (i != j && v != 0.0f) atomicExch(&s_offdiag, 1);
    __syncthreads();
    if (t == 0) g_is_diag = (s_offdiag == 0) ? 1 : 0;
}

// One thread per 16-float tile. Diagonal fast path (elementwise scale) or
// general 16x16 per-tile matmul fallback; branch is uniform across the grid.
__global__ void __launch_bounds__(256)
had_main_kernel(const float4* __restrict__ x, float4* __restrict__ out,
                int n_tiles) {
    __shared__ float s_ht[256];
    __shared__ float s_diag[16];
    __shared__ int   s_flag;

    int t = threadIdx.x;
    s_ht[t] = g_ht[t];                 // blockDim.x == 256 exactly
    if (t < 16) s_diag[t] = g_diag[t];
    if (t == 0) s_flag = g_is_diag;
    __syncthreads();

    int tile = blockIdx.x * 256 + t;
    if (tile >= n_tiles) return;

    long base = (long)tile * 4;        // float4 index
    // Front-batch all 4 vector loads (MLP = 4).
    float4 a = x[base + 0];
    float4 b = x[base + 1];
    float4 c = x[base + 2];
    float4 d = x[base + 3];

    float xv[16] = {a.x, a.y, a.z, a.w,
                    b.x, b.y, b.z, b.w,
                    c.x, c.y, c.z, c.w,
                    d.x, d.y, d.z, d.w};
    float o[16];

    if (s_flag) {
        #pragma unroll
        for (int j = 0; j < 16; ++j)
            o[j] = xv[j] * s_diag[j];
    } else {
        #pragma unroll
        for (int j = 0; j < 16; ++j) {
            float acc = 0.0f;
            #pragma unroll
            for (int i = 0; i < 16; ++i)
                acc = fmaf(xv[i], s_ht[j * 16 + i], acc);
            o[j] = acc;
        }
    }

    out[base + 0] = make_float4(o[0],  o[1],  o[2],  o[3]);
    out[base + 1] = make_float4(o[4],  o[5],  o[6],  o[7]);
    out[base + 2] = make_float4(o[8],  o[9],  o[10], o[11]);
    out[base + 3] = make_float4(o[12], o[13], o[14], o[15]);
}

extern "C" void kernel_launch(void* const* d_in, const int* in_sizes, int n_in,
                              void* d_out, int out_size) {
    const float* x        = (const float*)d_in[0];  // [4, 4096, 4096] f32
    const float* hadamard = (const float*)d_in[1];  // [16, 16] f32
    const float* signs    = (const float*)d_in[2];  // [16] f32
    float* out = (float*)d_out;

    int n_elems = in_sizes[0];
    int n_tiles = n_elems / 16;

    had_prep_kernel<<<1, 256>>>(hadamard, signs);

    int blocks = (n_tiles + 255) / 256;
    had_main_kernel<<<blocks, 256>>>((const float4*)x, (float4*)out, n_tiles);
}